// round 2
// baseline (speedup 1.0000x reference)
#include <cuda_runtime.h>
#include <cstdint>
#include <cstddef>

// ---------------- problem dims ----------------
#define TB   16384   // batch
#define TD   1024    // input dim
#define TH1  256
#define TH2  128
#define TGH  64
#define TNS  4
#define TDE  2
#define TDC  3
#define TNE  10      // total experts (4 shared + 6 domain)
#define NCOL  2752   // 10*256 + 3*64 (stage-1 output columns)
#define NCOLP 2816   // padded to 22*128

// ---------------- device scratch (allocation-free) ----------------
__device__ float g_W1t[(size_t)NCOLP * TD];      // [n][k]  (K-major), zero-padded cols
__device__ float g_b1[NCOLP];
__device__ float g_W2t[(size_t)TNE * TH2 * TH1]; // [e][n=h2][k=h1]
__device__ float g_b2[TNE * TH2];
__device__ float g_H[(size_t)TB * NCOLP];        // stage-1 activations (relu)
__device__ float g_O[(size_t)TNE * TB * TH2];    // stage-2 expert outputs (relu)
__device__ float g_gates[(size_t)TDC * TB * 6];  // softmax gates

// ---------------- helpers ----------------
__device__ __forceinline__ uint32_t f2tf(float f) {
    uint32_t u;
    asm("cvt.rna.tf32.f32 %0, %1;" : "=r"(u) : "f"(f));
    return u;
}

__device__ __forceinline__ void mma8(float* c, const uint32_t* a, const uint32_t* b) {
    asm volatile(
        "mma.sync.aligned.m16n8k8.row.col.f32.tf32.tf32.f32 "
        "{%0,%1,%2,%3},{%4,%5,%6,%7},{%8,%9},{%0,%1,%2,%3};\n"
        : "+f"(c[0]), "+f"(c[1]), "+f"(c[2]), "+f"(c[3])
        : "r"(a[0]), "r"(a[1]), "r"(a[2]), "r"(a[3]),
          "r"(b[0]), "r"(b[1]));
}

// ---------------- weight repack (transpose to K-major) ----------------
__global__ void pack1(const float* __restrict__ sW1, const float* __restrict__ dW1,
                      const float* __restrict__ gW1, const float* __restrict__ sb1,
                      const float* __restrict__ db1, const float* __restrict__ gb1) {
    int idx = blockIdx.x * blockDim.x + threadIdx.x;
    const int total = NCOLP * TD;
    if (idx < total) {
        int n = idx / TD, k = idx % TD;
        float v = 0.f;
        if (n < TNE * TH1) {
            int e = n / TH1, h = n % TH1;
            v = (e < TNS) ? sW1[((size_t)e * TD + k) * TH1 + h]
                          : dW1[((size_t)(e - TNS) * TD + k) * TH1 + h];
        } else if (n < NCOL) {
            int r = n - TNE * TH1;
            v = gW1[((size_t)(r / TGH) * TD + k) * TGH + (r % TGH)];
        }
        g_W1t[(size_t)n * TD + k] = v;
    }
    if (idx < NCOLP) {
        int n = idx;
        float v = 0.f;
        if (n < TNE * TH1) {
            int e = n / TH1, h = n % TH1;
            v = (e < TNS) ? sb1[e * TH1 + h] : db1[(e - TNS) * TH1 + h];
        } else if (n < NCOL) {
            int r = n - TNE * TH1;
            v = gb1[(r / TGH) * TGH + (r % TGH)];
        }
        g_b1[n] = v;
    }
}

__global__ void pack2(const float* __restrict__ sW2, const float* __restrict__ dW2,
                      const float* __restrict__ sb2, const float* __restrict__ db2) {
    int idx = blockIdx.x * blockDim.x + threadIdx.x;
    if (idx < TNE * TH2 * TH1) {
        int e = idx / (TH2 * TH1);
        int r = idx % (TH2 * TH1);
        int n = r / TH1, k = r % TH1;     // n = h2, k = h1
        float v = (e < TNS) ? sW2[((size_t)e * TH1 + k) * TH2 + n]
                            : dW2[((size_t)(e - TNS) * TH1 + k) * TH2 + n];
        g_W2t[idx] = v;
    }
    if (idx < TNE * TH2) {
        int e = idx / TH2, n = idx % TH2;
        g_b2[idx] = (e < TNS) ? sb2[e * TH2 + n] : db2[(e - TNS) * TH2 + n];
    }
}

// ---------------- tiled TF32 mma.sync GEMM (+bias, +relu) ----------------
// PHASE 1: relu(x @ W1t^T + b1)   -> g_H   [16384, 2816]  (K=1024)
// PHASE 2: relu(H_e @ W2t_e^T + b2) -> g_O [e][16384,128]  (K=256, z = expert)
#define BM 128
#define BN 128
#define BK 16
#define SST 137   // 128 + 9 words of padding on the k-stride

template <int PHASE>
__global__ void __launch_bounds__(256, 2) gemm_kernel(const float* __restrict__ Ax) {
    __shared__ uint32_t As[2][BK][SST];
    __shared__ uint32_t Bs[2][BK][SST];

    constexpr int K   = (PHASE == 1) ? TD : TH1;
    constexpr int LDA = (PHASE == 1) ? TD : NCOLP;
    constexpr int LDC = (PHASE == 1) ? NCOLP : TH2;

    const int bx = blockIdx.x, by = blockIdx.y, bz = blockIdx.z;

    const float* A;
    const float* Bp;
    const float* bias;
    float* C;
    if (PHASE == 1) {
        A    = Ax + (size_t)by * BM * LDA;
        Bp   = g_W1t + (size_t)bx * BN * K;
        bias = g_b1 + bx * BN;
        C    = g_H + (size_t)by * BM * LDC + bx * BN;
    } else {
        A    = g_H + (size_t)bz * TH1 + (size_t)by * BM * LDA;
        Bp   = g_W2t + (size_t)bz * TH2 * TH1;
        bias = g_b2 + bz * TH2;
        C    = g_O + (size_t)bz * TB * TH2 + (size_t)by * BM * LDC;
    }

    const int tid  = threadIdx.x;
    const int warp = tid >> 5, lane = tid & 31;
    const int gq = lane >> 2, tq = lane & 3;           // mma fragment coords
    const int wm = (warp >> 2) * 64, wn = (warp & 3) * 32;
    const int lr = tid >> 2, lc4 = (tid & 3) * 4;      // gmem->smem coords

    float c[4][4][4];
#pragma unroll
    for (int i = 0; i < 4; i++)
#pragma unroll
        for (int j = 0; j < 4; j++)
#pragma unroll
            for (int q = 0; q < 4; q++) c[i][j][q] = 0.f;

    float4 ra[2], rb[2];

    auto LDG = [&](int kt) {
        const float* ap = A + (size_t)lr * LDA + kt * BK + lc4;
        ra[0] = *(const float4*)ap;
        ra[1] = *(const float4*)(ap + (size_t)64 * LDA);
        const float* bp = Bp + (size_t)lr * K + kt * BK + lc4;
        rb[0] = *(const float4*)bp;
        rb[1] = *(const float4*)(bp + (size_t)64 * K);
    };
    auto STS = [&](int s) {
        const float* fa0 = (const float*)&ra[0];
        const float* fa1 = (const float*)&ra[1];
        const float* fb0 = (const float*)&rb[0];
        const float* fb1 = (const float*)&rb[1];
#pragma unroll
        for (int j = 0; j < 4; j++) {
            As[s][lc4 + j][lr]      = f2tf(fa0[j]);
            As[s][lc4 + j][lr + 64] = f2tf(fa1[j]);
            Bs[s][lc4 + j][lr]      = f2tf(fb0[j]);
            Bs[s][lc4 + j][lr + 64] = f2tf(fb1[j]);
        }
    };
    auto COMP = [&](int s) {
#pragma unroll
        for (int ks = 0; ks < BK; ks += 8) {
            uint32_t a[4][4], b[4][2];
#pragma unroll
            for (int mf = 0; mf < 4; mf++) {
                int r0 = wm + mf * 16 + gq;
                a[mf][0] = As[s][ks + tq][r0];
                a[mf][1] = As[s][ks + tq][r0 + 8];
                a[mf][2] = As[s][ks + tq + 4][r0];
                a[mf][3] = As[s][ks + tq + 4][r0 + 8];
            }
#pragma unroll
            for (int nf = 0; nf < 4; nf++) {
                int n0 = wn + nf * 8 + gq;
                b[nf][0] = Bs[s][ks + tq][n0];
                b[nf][1] = Bs[s][ks + tq + 4][n0];
            }
#pragma unroll
            for (int mf = 0; mf < 4; mf++)
#pragma unroll
                for (int nf = 0; nf < 4; nf++)
                    mma8(c[mf][nf], a[mf], b[nf]);
        }
    };

    LDG(0);
    STS(0);
    __syncthreads();
    constexpr int KT = K / BK;
#pragma unroll 1
    for (int kt = 0; kt < KT; kt++) {
        if (kt + 1 < KT) LDG(kt + 1);
        COMP(kt & 1);
        if (kt + 1 < KT) STS((kt + 1) & 1);
        __syncthreads();
    }

    // epilogue: bias + relu, fp32 store (bias hoisted into registers)
    float bcol0[4], bcol1[4];
#pragma unroll
    for (int nf = 0; nf < 4; nf++) {
        int col = wn + nf * 8 + 2 * tq;
        bcol0[nf] = bias[col];
        bcol1[nf] = bias[col + 1];
    }
#pragma unroll
    for (int mf = 0; mf < 4; mf++) {
        int r0 = wm + mf * 16 + gq;
#pragma unroll
        for (int nf = 0; nf < 4; nf++) {
            int col = wn + nf * 8 + 2 * tq;
            float2 v0 = {fmaxf(c[mf][nf][0] + bcol0[nf], 0.f), fmaxf(c[mf][nf][1] + bcol1[nf], 0.f)};
            float2 v1 = {fmaxf(c[mf][nf][2] + bcol0[nf], 0.f), fmaxf(c[mf][nf][3] + bcol1[nf], 0.f)};
            *(float2*)(C + (size_t)r0 * LDC + col)       = v0;
            *(float2*)(C + (size_t)(r0 + 8) * LDC + col) = v1;
        }
    }
}

// ---------------- gate logits + softmax ----------------
// one warp per (domain, batch-row); gate hidden lives in g_H cols [2560, 2752)
__global__ void gates_kernel(const float* __restrict__ gW2, const float* __restrict__ gb2) {
    int warp = threadIdx.x >> 5, lane = threadIdx.x & 31;
    int row  = blockIdx.x * 8 + warp;        // row = g*TB + b, < 3*16384
    int gdx  = row >> 14;                    // TB = 2^14
    int b    = row & (TB - 1);

    const float* gh = g_H + (size_t)b * NCOLP + TNE * TH1 + gdx * TGH;
    float x0 = gh[lane], x1 = gh[lane + 32];

    const float* w = gW2 + gdx * TGH * 6;
    float lg[6];
#pragma unroll
    for (int j = 0; j < 6; j++) {
        float s = x0 * __ldg(w + lane * 6 + j) +
                  x1 * __ldg(w + (lane + 32) * 6 + j);
#pragma unroll
        for (int o = 16; o > 0; o >>= 1) s += __shfl_xor_sync(0xffffffffu, s, o);
        lg[j] = s + __ldg(gb2 + gdx * 6 + j);
    }
    float mx = lg[0];
#pragma unroll
    for (int j = 1; j < 6; j++) mx = fmaxf(mx, lg[j]);
    float e[6], sum = 0.f;
#pragma unroll
    for (int j = 0; j < 6; j++) { e[j] = expf(lg[j] - mx); sum += e[j]; }
    float inv = 1.f / sum;
#pragma unroll
    for (int j = 0; j < 6; j++)
        if (lane == j) g_gates[(size_t)row * 6 + j] = e[j] * inv;
}

// ---------------- gated combine ----------------
// out[g][b][h] = sum_{i<6} gate[g][b][i] * O[sel(g,i)][b][h]
__global__ void combine_kernel(float* __restrict__ out) {
    size_t idx = (size_t)blockIdx.x * 256 + threadIdx.x;  // < 3*16384*32 (float4 per thread)
    int h4     = (int)(idx & 31);
    size_t gb  = idx >> 5;                 // g*TB + b
    int b      = (int)(gb & (TB - 1));
    int gdx    = (int)(gb >> 14);

    const float* gt = g_gates + gb * 6;
    float w[6];
#pragma unroll
    for (int i = 0; i < 6; i++) w[i] = gt[i];

    float4 acc = {0.f, 0.f, 0.f, 0.f};
#pragma unroll
    for (int i = 0; i < 6; i++) {
        int e = (i < 4) ? i : (TNS + gdx * TDE + (i - 4));
        float4 o = *(const float4*)(g_O + ((size_t)e * TB + b) * TH2 + h4 * 4);
        acc.x += w[i] * o.x;
        acc.y += w[i] * o.y;
        acc.z += w[i] * o.z;
        acc.w += w[i] * o.w;
    }
    *(float4*)(out + gb * TH2 + h4 * 4) = acc;
}

// ---------------- launch ----------------
extern "C" void kernel_launch(void* const* d_in, const int* in_sizes, int n_in,
                              void* d_out, int out_size) {
    // robust to either input ordering (setup_inputs dict order has domain_ids at [1])
    int off = (n_in > 1 && in_sizes[1] == TB) ? 1 : 0;
    const float* x   = (const float*)d_in[0];
    const float* sW1 = (const float*)d_in[1 + off];
    const float* sb1 = (const float*)d_in[2 + off];
    const float* sW2 = (const float*)d_in[3 + off];
    const float* sb2 = (const float*)d_in[4 + off];
    const float* dW1 = (const float*)d_in[5 + off];
    const float* db1 = (const float*)d_in[6 + off];
    const float* dW2 = (const float*)d_in[7 + off];
    const float* db2 = (const float*)d_in[8 + off];
    const float* gW1 = (const float*)d_in[9 + off];
    const float* gb1 = (const float*)d_in[10 + off];
    const float* gW2 = (const float*)d_in[11 + off];
    const float* gb2 = (const float*)d_in[12 + off];

    pack1<<<(NCOLP * TD + 255) / 256, 256>>>(sW1, dW1, gW1, sb1, db1, gb1);
    pack2<<<(TNE * TH2 * TH1 + 255) / 256, 256>>>(sW2, dW2, sb2, db2);
    gemm_kernel<1><<<dim3(NCOLP / BN, TB / BM, 1), 256>>>(x);
    gemm_kernel<2><<<dim3(1, TB / BM, TNE), 256>>>(nullptr);
    gates_kernel<<<(TDC * TB) / 8, 256>>>(gW2, gb2);
    combine_kernel<<<(TDC * TB * 32) / 256, 256>>>((float*)d_out);
}

// round 6
// speedup vs baseline: 1.6654x; 1.6654x over previous
#include <cuda_runtime.h>
#include <cstdint>
#include <cstddef>

// ---------------- problem dims ----------------
#define TB   16384
#define TD   1024
#define TH1  256
#define TH2  128
#define TGH  64
#define TNS  4
#define TDE  2
#define TDC  3
#define TNE  10
#define NCOL  2752   // 10*256 + 3*64
#define NCOLP 2816   // 22*128

// ---------------- device scratch ----------------
// B operands prepacked as tf32 pairs {W[n][k], W[n][k+4]}:
//   g_W1p[bx(22)][kt(64)][ks(2)][nb(16)][lane(32)]  (uint2 pairs, stored as uint4[])
__device__ uint4 g_W1p[(size_t)22 * 64 * 512];   // 11.5 MB
__device__ uint4 g_W2p[(size_t)10 * 16 * 512];   // 1.25 MB
__device__ float g_b1[NCOLP];
__device__ float g_b2[TNE * TH2];
__device__ float g_H[(size_t)TB * NCOLP];
__device__ float g_O[(size_t)TNE * TB * TH2];
__device__ float g_gates[(size_t)TDC * TB * 6];

// ---------------- helpers ----------------
__device__ __forceinline__ uint32_t smem_u32(const void* p) {
    uint32_t a;
    asm("{ .reg .u64 t; cvta.to.shared.u64 t, %1; cvt.u32.u64 %0, t; }" : "=r"(a) : "l"(p));
    return a;
}
__device__ __forceinline__ uint32_t f2tf(float f) {
    uint32_t u;
    asm("cvt.rna.tf32.f32 %0, %1;" : "=r"(u) : "f"(f));
    return u;
}
__device__ __forceinline__ void mma8(float* c, const uint32_t* a, const uint32_t* b) {
    asm volatile(
        "mma.sync.aligned.m16n8k8.row.col.f32.tf32.tf32.f32 "
        "{%0,%1,%2,%3},{%4,%5,%6,%7},{%8,%9},{%0,%1,%2,%3};\n"
        : "+f"(c[0]), "+f"(c[1]), "+f"(c[2]), "+f"(c[3])
        : "r"(a[0]), "r"(a[1]), "r"(a[2]), "r"(a[3]),
          "r"(b[0]), "r"(b[1]));
}
__device__ __forceinline__ void cp16(uint32_t saddr, const void* g) {
    asm volatile("cp.async.cg.shared.global [%0], [%1], 16;" :: "r"(saddr), "l"(g));
}
#define CP_COMMIT() asm volatile("cp.async.commit_group;" ::: "memory")
#define CP_WAIT0()  asm volatile("cp.async.wait_group 0;" ::: "memory")

// XOR lane permutation for A quads: bijective; LDS.128 reads conflict-free
// (each 8-lane phase maps to 8 distinct bank-quads: low 3 bits xor'd by group id)
__device__ __forceinline__ int permA(int v) { return v ^ (v >> 3); }

// ---------------- pack1: W1 -> pair layout (tf32) + bias ----------------
__global__ void pack1(const float* __restrict__ sW1, const float* __restrict__ dW1,
                      const float* __restrict__ gW1, const float* __restrict__ sb1,
                      const float* __restrict__ db1, const float* __restrict__ gb1) {
    int idx = blockIdx.x * blockDim.x + threadIdx.x;   // pair index
    const int total = 22 * 64 * 2 * 16 * 32;
    if (idx < total) {
        int lane = idx & 31, nb = (idx >> 5) & 15, ks = (idx >> 9) & 1;
        int kt = (idx >> 10) & 63, bx = idx >> 16;
        int n = bx * 128 + nb * 8 + (lane >> 2);
        int k = kt * 16 + ks * 8 + (lane & 3);
        float v0 = 0.f, v1 = 0.f;
        if (n < TNE * TH1) {
            int e = n >> 8, h = n & 255;
            const float* W = (e < TNS) ? sW1 + (size_t)e * TD * TH1
                                       : dW1 + (size_t)(e - TNS) * TD * TH1;
            v0 = W[(size_t)k * TH1 + h];
            v1 = W[(size_t)(k + 4) * TH1 + h];
        } else if (n < NCOL) {
            int r = n - TNE * TH1, g = r >> 6, hh = r & 63;
            v0 = gW1[((size_t)g * TD + k) * TGH + hh];
            v1 = gW1[((size_t)g * TD + k + 4) * TGH + hh];
        }
        ((uint2*)g_W1p)[idx] = make_uint2(f2tf(v0), f2tf(v1));
    }
    if (idx < NCOLP) {
        int n = idx;
        float v = 0.f;
        if (n < TNE * TH1) {
            int e = n >> 8, h = n & 255;
            v = (e < TNS) ? sb1[e * TH1 + h] : db1[(e - TNS) * TH1 + h];
        } else if (n < NCOL) {
            int r = n - TNE * TH1;
            v = gb1[(r / TGH) * TGH + (r % TGH)];
        }
        g_b1[n] = v;
    }
}

// ---------------- pack2: W2 -> pair layout (tf32) + bias ----------------
__global__ void pack2(const float* __restrict__ sW2, const float* __restrict__ dW2,
                      const float* __restrict__ sb2, const float* __restrict__ db2) {
    int idx = blockIdx.x * blockDim.x + threadIdx.x;
    const int total = 10 * 16 * 2 * 16 * 32;
    if (idx < total) {
        int lane = idx & 31, nb = (idx >> 5) & 15, ks = (idx >> 9) & 1;
        int kt = (idx >> 10) & 15, e = idx >> 14;
        int n = nb * 8 + (lane >> 2);           // h2
        int k = kt * 16 + ks * 8 + (lane & 3);  // h1
        const float* W = (e < TNS) ? sW2 + (size_t)e * TH1 * TH2
                                   : dW2 + (size_t)(e - TNS) * TH1 * TH2;
        float v0 = W[(size_t)k * TH2 + n];
        float v1 = W[(size_t)(k + 4) * TH2 + n];
        ((uint2*)g_W2p)[idx] = make_uint2(f2tf(v0), f2tf(v1));
    }
    if (idx < TNE * TH2) {
        int e = idx / TH2, n = idx % TH2;
        g_b2[idx] = (e < TNS) ? sb2[e * TH2 + n] : db2[(e - TNS) * TH2 + n];
    }
}

// ---------------- HMMA tf32 GEMM, fragment-packed smem ----------------
// CTA: 128 threads (4 warps, 2x2), tile 128x128, BK=16, warp tile 64x64.
// PHASE 1: relu(x @ W1^T + b1) -> g_H;  PHASE 2: relu(H_e @ W2_e^T + b2) -> g_O
template <int PHASE>
__global__ void __launch_bounds__(128, 2) gemm_hmma(const float* __restrict__ Ax) {
    constexpr int K   = (PHASE == 1) ? TD : TH1;
    constexpr int KT  = K / 16;
    constexpr int LDA = (PHASE == 1) ? TD : NCOLP;
    constexpr int LDC = (PHASE == 1) ? NCOLP : TH2;

    __shared__ uint4 Abuf[2][512];   // [ks(2)][mb(8)][pos(32)] quads, 8KB/buf
    __shared__ uint4 Bbuf[2][512];   // [ks(2)][nb(16)][lane(32)] pairs, 8KB/buf

    const int tid = threadIdx.x;
    const int bx = blockIdx.x, by = blockIdx.y, bz = blockIdx.z;

    const float* A;
    const uint4* Bsrc;
    const float* bias;
    float* C;
    if (PHASE == 1) {
        A    = Ax + (size_t)by * 128 * LDA;
        Bsrc = g_W1p + (size_t)bx * 64 * 512;
        bias = g_b1 + bx * 128;
        C    = g_H + (size_t)by * 128 * LDC + bx * 128;
    } else {
        A    = g_H + (size_t)by * 128 * LDA + bz * TH1;
        Bsrc = g_W2p + (size_t)bz * 16 * 512;
        bias = g_b2 + bz * TH2;
        C    = g_O + (size_t)bz * TB * TH2 + (size_t)by * 128 * LDC;
    }

    // loader coords: t = mbt*16 + lgq*2 + cg
    const int cg  = tid & 1;          // ks half (cols 0-7 / 8-15 of ktile)
    const int lgq = (tid >> 1) & 7;
    const int mbt = tid >> 4;         // 0..7
    const int rLo = mbt * 16 + lgq;

    // compute coords
    const int w = tid >> 5, lane = tid & 31;
    const int gq = lane >> 2, tq = lane & 3;
    const int wmb = (w >> 1) * 4;     // mb base (m16 blocks)
    const int wnb = (w & 1) * 8;      // nb base (n8 blocks)
    const int permL = permA(lane);

    const uint32_t sB[2] = {smem_u32(&Bbuf[0][0]), smem_u32(&Bbuf[1][0])};

    float c[4][8][4];
#pragma unroll
    for (int i = 0; i < 4; i++)
#pragma unroll
        for (int j = 0; j < 8; j++)
#pragma unroll
            for (int q = 0; q < 4; q++) c[i][j][q] = 0.f;

    float4 v0, v1, v2, v3;

    auto LDGA = [&](int kt) {
        const float* ap = A + (size_t)rLo * LDA + kt * 16 + cg * 8;
        v0 = *(const float4*)ap;
        v1 = *(const float4*)(ap + 4);
        const float* ap2 = ap + 8 * LDA;
        v2 = *(const float4*)ap2;
        v3 = *(const float4*)(ap2 + 4);
    };
    auto CPB = [&](int kt, int buf) {
        const char* g = (const char*)(Bsrc + (size_t)kt * 512);
#pragma unroll
        for (int i = 0; i < 4; i++) {
            int ch = tid + 128 * i;
            cp16(sB[buf] + ch * 16, g + ch * 16);
        }
        CP_COMMIT();
    };
    auto STSA = [&](int buf) {
        const float* f0 = (const float*)&v0;
        const float* f1 = (const float*)&v1;
        const float* f2 = (const float*)&v2;
        const float* f3 = (const float*)&v3;
#pragma unroll
        for (int s = 0; s < 4; s++) {
            uint4 q = {f2tf(f0[s]), f2tf(f2[s]), f2tf(f1[s]), f2tf(f3[s])};
            Abuf[buf][(cg * 8 + mbt) * 32 + permA(4 * lgq + s)] = q;
        }
    };
    auto COMP = [&](int s) {
        const uint2* Bb = (const uint2*)&Bbuf[s][0];
        const uint4* Ab = &Abuf[s][0];
#pragma unroll
        for (int ks = 0; ks < 2; ks++) {
            uint4 a[4];
#pragma unroll
            for (int mf = 0; mf < 4; mf++)
                a[mf] = Ab[(ks * 8 + wmb + mf) * 32 + permL];
            uint2 b[8];
#pragma unroll
            for (int nf = 0; nf < 8; nf++)
                b[nf] = Bb[(ks * 16 + wnb + nf) * 32 + lane];
#pragma unroll
            for (int mf = 0; mf < 4; mf++)
#pragma unroll
                for (int nf = 0; nf < 8; nf++)
                    mma8(c[mf][nf], (const uint32_t*)&a[mf], (const uint32_t*)&b[nf]);
        }
    };

    // prologue: stage 0
    LDGA(0);
    CPB(0, 0);
    STSA(0);
    CP_WAIT0();
    __syncthreads();

#pragma unroll 1
    for (int kt = 0; kt < KT; kt++) {
        const int s = kt & 1;
        if (kt + 1 < KT) {
            LDGA(kt + 1);
            CPB(kt + 1, s ^ 1);
        }
        COMP(s);
        if (kt + 1 < KT) STSA(s ^ 1);
        CP_WAIT0();
        __syncthreads();
    }

    // epilogue: bias + relu
    const int wm = (w >> 1) * 64, wn = (w & 1) * 64;
    float b0r[8], b1r[8];
#pragma unroll
    for (int nf = 0; nf < 8; nf++) {
        int col = wn + nf * 8 + 2 * tq;
        b0r[nf] = bias[col];
        b1r[nf] = bias[col + 1];
    }
#pragma unroll
    for (int mf = 0; mf < 4; mf++) {
        int r0 = wm + mf * 16 + gq;
#pragma unroll
        for (int nf = 0; nf < 8; nf++) {
            int col = wn + nf * 8 + 2 * tq;
            float2 u0 = {fmaxf(c[mf][nf][0] + b0r[nf], 0.f), fmaxf(c[mf][nf][1] + b1r[nf], 0.f)};
            float2 u1 = {fmaxf(c[mf][nf][2] + b0r[nf], 0.f), fmaxf(c[mf][nf][3] + b1r[nf], 0.f)};
            *(float2*)(C + (size_t)r0 * LDC + col)       = u0;
            *(float2*)(C + (size_t)(r0 + 8) * LDC + col) = u1;
        }
    }
}

// ---------------- gates + softmax (unchanged, proven) ----------------
__global__ void gates_kernel(const float* __restrict__ gW2, const float* __restrict__ gb2) {
    int warp = threadIdx.x >> 5, lane = threadIdx.x & 31;
    int row  = blockIdx.x * 8 + warp;
    int gdx  = row >> 14;
    int b    = row & (TB - 1);

    const float* gh = g_H + (size_t)b * NCOLP + TNE * TH1 + gdx * TGH;
    float x0 = gh[lane], x1 = gh[lane + 32];

    const float* wght = gW2 + gdx * TGH * 6;
    float lg[6];
#pragma unroll
    for (int j = 0; j < 6; j++) {
        float s = x0 * __ldg(wght + lane * 6 + j) +
                  x1 * __ldg(wght + (lane + 32) * 6 + j);
#pragma unroll
        for (int o = 16; o > 0; o >>= 1) s += __shfl_xor_sync(0xffffffffu, s, o);
        lg[j] = s + __ldg(gb2 + gdx * 6 + j);
    }
    float mx = lg[0];
#pragma unroll
    for (int j = 1; j < 6; j++) mx = fmaxf(mx, lg[j]);
    float e[6], sum = 0.f;
#pragma unroll
    for (int j = 0; j < 6; j++) { e[j] = expf(lg[j] - mx); sum += e[j]; }
    float inv = 1.f / sum;
#pragma unroll
    for (int j = 0; j < 6; j++)
        if (lane == j) g_gates[(size_t)row * 6 + j] = e[j] * inv;
}

// ---------------- gated combine (unchanged, proven) ----------------
__global__ void combine_kernel(float* __restrict__ out) {
    size_t idx = (size_t)blockIdx.x * 256 + threadIdx.x;
    int h4     = (int)(idx & 31);
    size_t gb  = idx >> 5;
    int b      = (int)(gb & (TB - 1));
    int gdx    = (int)(gb >> 14);

    const float* gt = g_gates + gb * 6;
    float w[6];
#pragma unroll
    for (int i = 0; i < 6; i++) w[i] = gt[i];

    float4 acc = {0.f, 0.f, 0.f, 0.f};
#pragma unroll
    for (int i = 0; i < 6; i++) {
        int e = (i < 4) ? i : (TNS + gdx * TDE + (i - 4));
        float4 o = *(const float4*)(g_O + ((size_t)e * TB + b) * TH2 + h4 * 4);
        acc.x += w[i] * o.x;
        acc.y += w[i] * o.y;
        acc.z += w[i] * o.z;
        acc.w += w[i] * o.w;
    }
    *(float4*)(out + gb * TH2 + h4 * 4) = acc;
}

// ---------------- launch ----------------
extern "C" void kernel_launch(void* const* d_in, const int* in_sizes, int n_in,
                              void* d_out, int out_size) {
    int off = (n_in > 1 && in_sizes[1] == TB) ? 1 : 0;
    const float* x   = (const float*)d_in[0];
    const float* sW1 = (const float*)d_in[1 + off];
    const float* sb1 = (const float*)d_in[2 + off];
    const float* sW2 = (const float*)d_in[3 + off];
    const float* sb2 = (const float*)d_in[4 + off];
    const float* dW1 = (const float*)d_in[5 + off];
    const float* db1 = (const float*)d_in[6 + off];
    const float* dW2 = (const float*)d_in[7 + off];
    const float* db2 = (const float*)d_in[8 + off];
    const float* gW1 = (const float*)d_in[9 + off];
    const float* gb1 = (const float*)d_in[10 + off];
    const float* gW2 = (const float*)d_in[11 + off];
    const float* gb2 = (const float*)d_in[12 + off];

    const int np1 = 22 * 64 * 2 * 16 * 32;
    const int np2 = 10 * 16 * 2 * 16 * 32;
    pack1<<<(np1 + 255) / 256, 256>>>(sW1, dW1, gW1, sb1, db1, gb1);
    pack2<<<(np2 + 255) / 256, 256>>>(sW2, dW2, sb2, db2);
    gemm_hmma<1><<<dim3(22, 128, 1), 128>>>(x);
    gemm_hmma<2><<<dim3(1, 128, 10), 128>>>(nullptr);
    gates_kernel<<<(TDC * TB) / 8, 256>>>(gW2, gb2);
    combine_kernel<<<(TDC * TB * 32) / 256, 256>>>((float*)d_out);
}